// round 5
// baseline (speedup 1.0000x reference)
#include <cuda_runtime.h>
#include <math.h>

#define RIR_LENGTH 3968
#define NBLK4      992           // RIR_LENGTH / 4 (exact)
#define PAD        40
#define BATCH      128
#define MAXO       15
#define GRID_N     31
#define GRID_TOT   (31*31*31)    // 29791
#define NIMG       4991          // |x|+|y|+|z| <= 15 lattice points
#define FSR        46.64723032f  // fp32(16000/343)
#define INV_PI     0.3183098862f

#define NWARP   3
#define TPB     (NWARP*32)       // 96
#define SPLIT   5
#define WG_TOT  (SPLIT*NWARP)    // 15 warp-groups per batch
#define CHUNK   ((NIMG + WG_TOT - 1) / WG_TOT)   // 333

__device__ int g_xyz[NIMG + 8];
__device__ int g_cnt;

// ---------------------------------------------------------------------------
__global__ void k_reset() { g_cnt = 0; }

__global__ void k_build() {
    int idx = blockIdx.x * blockDim.x + threadIdx.x;
    if (idx >= GRID_TOT) return;
    int ix = idx % GRID_N - MAXO;
    int iy = (idx / GRID_N) % GRID_N - MAXO;
    int iz = idx / (GRID_N * GRID_N) - MAXO;
    if (abs(ix) + abs(iy) + abs(iz) <= MAXO) {
        int p = atomicAdd(&g_cnt, 1);
        if (p < NIMG)
            g_xyz[p] = (ix + 16) | ((iy + 16) << 8) | ((iz + 16) << 16);
    }
}

// Zero the rir region of d_out and compute toa.
__global__ void k_init(const float* __restrict__ inp, float* __restrict__ out) {
    int i = blockIdx.x * blockDim.x + threadIdx.x;
    int total = BATCH * RIR_LENGTH;
    for (int j = i; j < total; j += gridDim.x * blockDim.x) out[j] = 0.0f;
    if (i < BATCH) {
        const float* r = inp + i * 12;
        float dx = __fsub_rn(__fmul_rn(r[3], r[0]), __fmul_rn(r[6], r[0]));
        float dy = __fsub_rn(__fmul_rn(r[4], r[1]), __fmul_rn(r[7], r[1]));
        float dz = __fsub_rn(__fmul_rn(r[5], r[2]), __fmul_rn(r[8], r[2]));
        float ss = __fadd_rn(__fadd_rn(__fmul_rn(dx, dx), __fmul_rn(dy, dy)),
                             __fmul_rn(dz, dz));
        float dist = __fsqrt_rn(ss);
        out[total + i] = __fadd_rn((float)PAD, __fmul_rn(dist, FSR));
    }
}

// ---------------------------------------------------------------------------
__global__ __launch_bounds__(TPB) void k_main(const float* __restrict__ inp,
                                              float* __restrict__ out) {
    __shared__ __align__(16) float sm[NWARP * RIR_LENGTH];   // per-warp private RIRs
    __shared__ float sPW[16], sPL[9], sPH[9], sGeo[9];

    const int b    = blockIdx.y;
    const int tid  = threadIdx.x;
    const int warp = tid >> 5;
    const int lane = tid & 31;
    float* srw = sm + warp * RIR_LENGTH;

    // zero private copies (float4)
    {
        float4* smv = (float4*)sm;
        float4 z = make_float4(0.f, 0.f, 0.f, 0.f);
        for (int j = tid; j < NWARP * NBLK4; j += TPB) smv[j] = z;
    }

    if (tid == 0) {
        const float* r = inp + b * 12;
        float rx = r[0], ry = r[1], rz = r[2];
        sGeo[0] = rx;                  sGeo[1] = ry;                  sGeo[2] = rz;
        sGeo[3] = __fmul_rn(r[3], rx); sGeo[4] = __fmul_rn(r[4], ry); sGeo[5] = __fmul_rn(r[5], rz);
        sGeo[6] = __fmul_rn(r[6], rx); sGeo[7] = __fmul_rn(r[7], ry); sGeo[8] = __fmul_rn(r[8], rz);
        float aw  = __fadd_rn(__fmul_rn(r[9],  0.84f), 0.01f);
        float a4  = __fadd_rn(__fmul_rn(r[10], 0.84f), 0.01f);
        float a5  = __fadd_rn(__fmul_rn(r[11], 0.84f), 0.01f);
        double trw = sqrt(1.0 - (double)aw);
        double tr4 = sqrt(1.0 - (double)a4);
        double tr5 = sqrt(1.0 - (double)a5);
        double p = 1.0;
        for (int e = 0; e < 16; e++) { sPW[e] = (float)p; p *= trw; }
        p = 1.0;
        for (int e = 0; e < 9;  e++) { sPL[e] = (float)p; p *= tr4; }
        p = 1.0;
        for (int e = 0; e < 9;  e++) { sPH[e] = (float)p; p *= tr5; }
    }
    __syncthreads();

    // per-lane constants: cos/sin(pi*(4L+t)/40), t = 0..3
    float cc0, ss0, cc1, ss1, cc2, ss2, cc3, ss3;
    {
        float a = (float)(4 * lane) * 0.025f;
        sincospif(a,           &ss0, &cc0);
        sincospif(a + 0.025f,  &ss1, &cc1);
        sincospif(a + 0.050f,  &ss2, &cc2);
        sincospif(a + 0.075f,  &ss3, &cc3);
    }
    const float fl4    = (float)(4 * lane);
    const int   k0base = 4 * lane;

    const float d0 = sGeo[0], d1 = sGeo[1], d2 = sGeo[2];
    const float m0 = sGeo[3], m1 = sGeo[4], m2 = sGeo[5];
    const float s0 = sGeo[6], s1 = sGeo[7], s2v = sGeo[8];

    const int wg   = blockIdx.x * NWARP + warp;
    const int ibeg = wg * CHUNK;
    const int iend = min(ibeg + CHUNK, NIMG);

    for (int i0 = ibeg; i0 < iend; i0 += 32) {
        // ---- prologue: each lane preps one image ----
        int   f_code = 2;                 // 2 = skip
        int   f_t0 = 0;
        float f_psi = 0.f, f_cph = 1.f, f_sph = 0.f, f_A = 0.f, f_amp = 0.f;
        int i = i0 + lane;
        if (i < iend) {
            int pk = g_xyz[i];
            int ix = (pk & 255) - 16;
            int iy = ((pk >> 8) & 255) - 16;
            int iz = (pk >> 16) - 16;

            float img0 = (ix & 1) ? __fsub_rn(__fmul_rn(d0, (float)(ix + 1)), s0)
                                  : __fadd_rn(__fmul_rn(d0, (float)ix), s0);
            float img1 = (iy & 1) ? __fsub_rn(__fmul_rn(d1, (float)(iy + 1)), s1)
                                  : __fadd_rn(__fmul_rn(d1, (float)iy), s1);
            float img2 = (iz & 1) ? __fsub_rn(__fmul_rn(d2, (float)(iz + 1)), s2v)
                                  : __fadd_rn(__fmul_rn(d2, (float)iz), s2v);
            float e0 = __fsub_rn(img0, m0);
            float e1 = __fsub_rn(img1, m1);
            float e2 = __fsub_rn(img2, m2);
            float ssq = __fadd_rn(__fadd_rn(__fmul_rn(e0, e0), __fmul_rn(e1, e1)),
                                  __fmul_rn(e2, e2));
            float dist  = __fsqrt_rn(ssq);
            float delay = __fmul_rn(dist, FSR);
            float di    = ceilf(delay);
            int   t0    = (int)di - PAD;
            if (t0 < RIR_LENGTH) {
                int axy  = abs(ix) + abs(iy);
                int elo2 = (iz >= 0) ? (iz >> 1)       : ((-iz + 1) >> 1);
                int ehi2 = (iz >= 0) ? ((iz + 1) >> 1) : ((-iz) >> 1);
                float att = sPW[axy] * sPL[elo2] * sPH[ehi2];
                float amp = __fdiv_rn(att, dist);
                float frac = __fsub_rn(di, delay);
                f_t0 = t0; f_amp = amp;
                if (frac == 0.0f) {
                    f_code = 1;
                } else {
                    f_code = 0;
                    int off = t0 & 3;
                    float psi = frac - 40.0f - (float)off;
                    f_psi = psi;
                    sincospif(psi * 0.025f, &f_sph, &f_cph);
                    f_A = amp * sinpif(frac) * INV_PI;
                }
            }
        }
        // ---- consume the 32 images warp-cooperatively ----
        int nh = min(32, iend - i0);
        for (int j = 0; j < nh; j++) {
            int code = __shfl_sync(0xffffffffu, f_code, j);
            if (code == 2) continue;
            int bt0 = __shfl_sync(0xffffffffu, f_t0, j);
            if (code == 1) {                       // pure spike
                float bamp = __shfl_sync(0xffffffffu, f_amp, j);
                int di = bt0 + PAD;
                if (lane == 0 && di < RIR_LENGTH) srw[di] += bamp;
                continue;
            }
            float bpsi = __shfl_sync(0xffffffffu, f_psi, j);
            float bcph = __shfl_sync(0xffffffffu, f_cph, j);
            float bsph = __shfl_sync(0xffffffffu, f_sph, j);
            float bA   = __shfl_sync(0xffffffffu, f_A,   j);
            int off = bt0 & 3;
            if (bt0 >= 0) {
                // aligned float4-block scatter; lanes 0..20 cover the window
                float Ae = (off & 1) ? -0.5f * bA : 0.5f * bA;
                float Ao = -Ae;
                int   blk = (bt0 >> 2) + lane;
                int   k0  = k0base - off;
                float x0 = bpsi + fl4;
                float x1 = x0 + 1.0f, x2 = x0 + 2.0f, x3 = x0 + 3.0f;
                float w0 = cc0 * bcph - ss0 * bsph;
                float w1 = cc1 * bcph - ss1 * bsph;
                float w2 = cc2 * bcph - ss2 * bsph;
                float w3 = cc3 * bcph - ss3 * bsph;
                float u0 = fmaf(Ae, w0, Ae);
                float u1 = fmaf(Ao, w1, Ao);
                float u2 = fmaf(Ae, w2, Ae);
                float u3 = fmaf(Ao, w3, Ao);
                u0 = ((unsigned)k0       <= 79u) ? u0 : 0.0f;
                u1 = ((unsigned)(k0 + 1) <= 79u) ? u1 : 0.0f;
                u2 = ((unsigned)(k0 + 2) <= 79u) ? u2 : 0.0f;
                u3 = ((unsigned)(k0 + 3) <= 79u) ? u3 : 0.0f;
                if (lane <= 20 && blk < NBLK4) {
                    float r01 = __fdividef(1.0f, x0 * x1);
                    float r23 = __fdividef(1.0f, x2 * x3);
                    float4* p4 = (float4*)srw + blk;
                    float4 f = *p4;
                    f.x += (u0 * x1) * r01;
                    f.y += (u1 * x0) * r01;
                    f.z += (u2 * x3) * r23;
                    f.w += (u3 * x2) * r23;
                    *p4 = f;
                }
            } else {
                // rare near-field path: JAX negative-index wrap, scalar per-lane taps
                float frac40 = bpsi + (float)off;      // frac - 40
                #pragma unroll
                for (int m = 0; m < 3; m++) {
                    int k = lane + 32 * m;
                    if (k <= 79) {
                        float x  = frac40 + (float)k;
                        float w  = cospif(x * 0.025f);
                        float sg = (k & 1) ? -0.5f * bA : 0.5f * bA;
                        float u  = fmaf(sg, w, sg);
                        float v  = u * __fdividef(1.0f, x);
                        int idx = bt0 + k;
                        if (idx < 0) idx += RIR_LENGTH;
                        srw[idx] += v;                 // lane-disjoint indices
                    }
                }
            }
        }
    }
    __syncthreads();

    // epilogue: sum the NWARP private copies, one global atomic per bin
    float* orir = out + b * RIR_LENGTH;
    for (int j = tid; j < RIR_LENGTH; j += TPB) {
        float v = sm[j] + sm[RIR_LENGTH + j] + sm[2 * RIR_LENGTH + j];
        if (v != 0.0f) atomicAdd(&orir[j], v);
    }
}

// ---------------------------------------------------------------------------
extern "C" void kernel_launch(void* const* d_in, const int* in_sizes, int n_in,
                              void* d_out, int out_size) {
    const float* inp = (const float*)d_in[0];
    float* out = (float*)d_out;

    k_reset<<<1, 1>>>();
    k_build<<<(GRID_TOT + 255) / 256, 256>>>();
    k_init<<<512, 256>>>(inp, out);
    k_main<<<dim3(SPLIT, BATCH), TPB>>>(inp, out);
}